// round 7
// baseline (speedup 1.0000x reference)
#include <cuda_runtime.h>
#include <cuda_bf16.h>
#include <cstdint>

// ---------------------------------------------------------------------------
// NetVLAD on GB300 — round 6: fully-async conv fills. Activations live as
// hi/lo bf16 planes in transposed halo-padded layout [pos_padded][c], so both
// A and B tiles are pure cp.async copies; 2-stage pipelined mainloop.
// ---------------------------------------------------------------------------

#define N_IMG   16
#define CHN     512
#define HWP     1024
#define KCL     64
#define KTOT    4608
#define AP      40          // SMEM row pitch in bf16 (80B)
#define PPOS    1156        // 34*34 padded positions
#define PLANE_N (PPOS * CHN)

// stage layout (bytes): Ah 0, Al 10240, Bh 20480, Bl 30720
#define STAGE_BYTES 40960
#define OFF_AL 10240
#define OFF_BH 20480
#define OFF_BL 30720
#define CONV_DSMEM (2 * STAGE_BYTES)

// -------- device scratch --------
__device__ __align__(16) __nv_bfloat16 g_w1h[CHN * KTOT];
__device__ __align__(16) __nv_bfloat16 g_w1l[CHN * KTOT];
__device__ __align__(16) __nv_bfloat16 g_w2h[CHN * KTOT];
__device__ __align__(16) __nv_bfloat16 g_w2l[CHN * KTOT];
// activation planes, halo-padded + transposed: [n][(y+1)*34+(x+1)][c]
__device__ __align__(16) __nv_bfloat16 g_xh[N_IMG * PLANE_N];
__device__ __align__(16) __nv_bfloat16 g_xl[N_IMG * PLANE_N];
__device__ __align__(16) __nv_bfloat16 g_hh[N_IMG * PLANE_N];
__device__ __align__(16) __nv_bfloat16 g_hl[N_IMG * PLANE_N];
__device__ float g_invn[N_IMG * HWP];
__device__ float g_sa[N_IMG * KCL * HWP];
__device__ float g_ssum[N_IMG * KCL];
__device__ float g_vlad[N_IMG * KCL * CHN];
__device__ float g_rowss[N_IMG * KCL];
__device__ float g_bns[CHN];
__device__ float g_bnb[CHN];

// -------- helpers --------
__device__ __forceinline__ uint32_t smem_u32(const void* p) {
    uint32_t a;
    asm("{ .reg .u64 t; cvta.to.shared.u64 t, %1; cvt.u32.u64 %0, t; }"
        : "=r"(a) : "l"(p));
    return a;
}
__device__ __forceinline__ void ldm_x4(uint32_t r[4], uint32_t addr) {
    asm volatile("ldmatrix.sync.aligned.m8n8.x4.shared.b16 {%0,%1,%2,%3}, [%4];"
                 : "=r"(r[0]), "=r"(r[1]), "=r"(r[2]), "=r"(r[3]) : "r"(addr));
}
__device__ __forceinline__ void mma_bf16(float c[4], const uint32_t a[4],
                                         uint32_t b0, uint32_t b1) {
    asm volatile(
        "mma.sync.aligned.m16n8k16.row.col.f32.bf16.bf16.f32 "
        "{%0,%1,%2,%3}, {%4,%5,%6,%7}, {%8,%9}, {%0,%1,%2,%3};"
        : "+f"(c[0]), "+f"(c[1]), "+f"(c[2]), "+f"(c[3])
        : "r"(a[0]), "r"(a[1]), "r"(a[2]), "r"(a[3]), "r"(b0), "r"(b1));
}
__device__ __forceinline__ void cp_async16(uint32_t dst, const void* src) {
    asm volatile("cp.async.cg.shared.global [%0], [%1], 16;"
                 :: "r"(dst), "l"(src));
}
#define CP_COMMIT() asm volatile("cp.async.commit_group;" ::: "memory")
#define CP_WAIT(n)  asm volatile("cp.async.wait_group %0;" :: "n"(n) : "memory")

__device__ __forceinline__ uint32_t pack_hl(float v) {
    __nv_bfloat16 h = __float2bfloat16(v);
    __nv_bfloat16 l = __float2bfloat16(v - __bfloat162float(h));
    return (uint32_t)__bfloat16_as_ushort(h) |
           ((uint32_t)__bfloat16_as_ushort(l) << 16);
}

// ======================= prep: weight hi/lo split + BN fold ================
__global__ void prep_kernel(const float* __restrict__ w1,
                            const float* __restrict__ w2,
                            const float* __restrict__ gamma,
                            const float* __restrict__ beta,
                            const float* __restrict__ mean,
                            const float* __restrict__ var) {
    int idx = blockIdx.x * 256 + threadIdx.x;
    const int per = CHN * KTOT;
    if (idx < 2 * per) {
        int which = (idx >= per) ? 1 : 0;
        int r = idx - which * per;
        int oc = r / KTOT;
        int rr = r - oc * KTOT;
        int tap = rr >> 9;
        int ic = rr & 511;
        const float* w = which ? w2 : w1;
        float v = w[oc * 4608 + ic * 9 + tap];
        __nv_bfloat16 h = __float2bfloat16(v);
        __nv_bfloat16 l = __float2bfloat16(v - __bfloat162float(h));
        if (which) { g_w2h[r] = h; g_w2l[r] = l; }
        else       { g_w1h[r] = h; g_w1l[r] = l; }
    }
    if (idx < CHN) {
        float inv = rsqrtf(var[idx] + 1e-5f);
        float s = gamma[idx] * inv;
        g_bns[idx] = s;
        g_bnb[idx] = beta[idx] - mean[idx] * s;
    }
}

// ======================= pack x: fp32 [c][pos] -> planes [pos_pad][c] ======
// grid: (16 cblk, 32 y, 16 n); block 256. Tile: 32 c x 32 x, SMEM transpose.
__global__ void __launch_bounds__(256)
pack_x_kernel(const float* __restrict__ x) {
    __shared__ float sm[32][33];
    const int cblk = blockIdx.x, y = blockIdx.y, n = blockIdx.z;
    const int tid = threadIdx.x;
    const float* xN = x + (size_t)n * CHN * HWP;

    const int cc = tid >> 5, tx = tid & 31;
#pragma unroll
    for (int r = 0; r < 4; r++) {
        int c = cblk * 32 + cc + r * 8;
        sm[cc + r * 8][tx] = xN[(size_t)c * HWP + y * 32 + tx];
    }
    __syncthreads();
    const int tc = tid & 31, ty = tid >> 5;
    size_t pb = (size_t)n * PLANE_N;
#pragma unroll
    for (int r = 0; r < 4; r++) {
        int xq = ty + r * 8;
        float v = sm[tc][xq];
        __nv_bfloat16 h = __float2bfloat16(v);
        __nv_bfloat16 l = __float2bfloat16(v - __bfloat162float(h));
        size_t off = pb + (size_t)((y + 1) * 34 + xq + 1) * CHN + cblk * 32 + tc;
        g_xh[off] = h;
        g_xl[off] = l;
    }
}

// ======================= conv3x3: fully-async pipelined mma.sync bf16x3 ====
__global__ void __launch_bounds__(256, 2)
conv_mma_kernel(float* __restrict__ out_ext, int which) {
    extern __shared__ __align__(16) char dynsm[];
    const uint32_t smbase = smem_u32(dynsm);

    const int tid = threadIdx.x;
    const int lane = tid & 31, warp = tid >> 5;
    const int wm = warp >> 2, wn = warp & 3;
    const int n = blockIdx.z;
    const int oc0 = blockIdx.y * 128;
    const int p0 = blockIdx.x * 128;
    const int ybase = blockIdx.x * 4;

    const __nv_bfloat16* xh =
        ((which == 1) ? g_xh : g_hh) + (size_t)n * PLANE_N;
    const __nv_bfloat16* xl =
        ((which == 1) ? g_xl : g_hl) + (size_t)n * PLANE_N;
    const __nv_bfloat16* wh = (which == 1) ? g_w1h : g_w2h;
    const __nv_bfloat16* wl = (which == 1) ? g_w1l : g_w2l;

    const int frow = tid >> 1, fhalf = tid & 1;   // 128 rows, 2 threads/row

    const int lt = lane >> 3, lr = lane & 7;
    const int a_row_off = (lt & 1) * 8 + lr;
    const int a_col_off = (lt >> 1) * 8;
    const int b_row_off = (lt >> 1) * 8 + lr;
    const int b_col_off = (lt & 1) * 8;

    float C[4][4][4];
#pragma unroll
    for (int mi = 0; mi < 4; mi++)
#pragma unroll
        for (int ni = 0; ni < 4; ni++)
#pragma unroll
            for (int q = 0; q < 4; q++) C[mi][ni][q] = 0.f;

    // per-chunk fill: 8 cp.async.16 per thread (A hi/lo + B hi/lo)
    auto fill = [&](int chunk, int stage) {
        const int k0 = chunk << 5;
        const int tap = chunk >> 4;            // 16 chunks per tap
        const int icb = (chunk & 15) << 5;
        const int dy = tap / 3 - 1, dx = tap % 3 - 1;
        const uint32_t sb = smbase + stage * STAGE_BYTES;
        // A
        {
            const __nv_bfloat16* sH =
                wh + (size_t)(oc0 + frow) * KTOT + k0 + fhalf * 16;
            const __nv_bfloat16* sL =
                wl + (size_t)(oc0 + frow) * KTOT + k0 + fhalf * 16;
            uint32_t d = sb + frow * 80 + fhalf * 32;
            cp_async16(d, sH);
            cp_async16(d + 16, sH + 8);
            cp_async16(d + OFF_AL, sL);
            cp_async16(d + OFF_AL + 16, sL + 8);
        }
        // B (halo-padded planes: always in-bounds, halo = 0)
        {
            int srow = (ybase + (frow >> 5) + dy + 1) * 34 +
                       (frow & 31) + dx + 1;
            const __nv_bfloat16* sH = xh + (size_t)srow * CHN + icb + fhalf * 16;
            const __nv_bfloat16* sL = xl + (size_t)srow * CHN + icb + fhalf * 16;
            uint32_t d = sb + frow * 80 + fhalf * 32;
            cp_async16(d + OFF_BH, sH);
            cp_async16(d + OFF_BH + 16, sH + 8);
            cp_async16(d + OFF_BL, sL);
            cp_async16(d + OFF_BL + 16, sL + 8);
        }
    };

    // prologue: 2 stages in flight
    fill(0, 0); CP_COMMIT();
    fill(1, 1); CP_COMMIT();

    for (int chunk = 0; chunk < 144; ++chunk) {
        const int stage = chunk & 1;
        if (chunk == 143) { CP_WAIT(0); } else { CP_WAIT(1); }
        __syncthreads();

        const uint32_t sb = smbase + stage * STAGE_BYTES;
#pragma unroll
        for (int s = 0; s < 2; ++s) {
            const int kk0 = s * 16;
            uint32_t Af[4][4], Bhf[2][4], Blf[2][4];
#pragma unroll
            for (int mi = 0; mi < 4; mi++) {
                int row = wm * 64 + mi * 16 + a_row_off;
                ldm_x4(Af[mi], sb + (uint32_t)(row * AP + kk0 + a_col_off) * 2);
            }
#pragma unroll
            for (int g = 0; g < 2; g++) {
                int row = wn * 32 + g * 16 + b_row_off;
                uint32_t off = (uint32_t)(row * AP + kk0 + b_col_off) * 2;
                ldm_x4(Bhf[g], sb + OFF_BH + off);
                ldm_x4(Blf[g], sb + OFF_BL + off);
            }
#pragma unroll
            for (int mi = 0; mi < 4; mi++)
#pragma unroll
                for (int ni = 0; ni < 4; ni++)
                    mma_bf16(C[mi][ni], Af[mi],
                             Bhf[ni >> 1][(ni & 1) * 2],
                             Bhf[ni >> 1][(ni & 1) * 2 + 1]);
#pragma unroll
            for (int mi = 0; mi < 4; mi++)
#pragma unroll
                for (int ni = 0; ni < 4; ni++)
                    mma_bf16(C[mi][ni], Af[mi],
                             Blf[ni >> 1][(ni & 1) * 2],
                             Blf[ni >> 1][(ni & 1) * 2 + 1]);
#pragma unroll
            for (int mi = 0; mi < 4; mi++) {
                int row = wm * 64 + mi * 16 + a_row_off;
                ldm_x4(Af[mi],
                       sb + OFF_AL + (uint32_t)(row * AP + kk0 + a_col_off) * 2);
            }
#pragma unroll
            for (int mi = 0; mi < 4; mi++)
#pragma unroll
                for (int ni = 0; ni < 4; ni++)
                    mma_bf16(C[mi][ni], Af[mi],
                             Bhf[ni >> 1][(ni & 1) * 2],
                             Bhf[ni >> 1][(ni & 1) * 2 + 1]);
        }

        if (chunk + 2 < 144) {
            __syncthreads();           // everyone done reading this stage
            fill(chunk + 2, stage);    // refill it for chunk+2
            CP_COMMIT();
        }
    }

    // ---- epilogue ----
    const int g = lane >> 2, t4 = lane & 3;
    if (which == 1) {
        // BN+ReLU, pack hi/lo, transpose through SMEM -> planes [pos][c]
        uint32_t* smT = reinterpret_cast<uint32_t*>(dynsm);  // pitch 132
        __syncthreads();
#pragma unroll
        for (int mi = 0; mi < 4; mi++) {
            int ocAl = wm * 64 + mi * 16 + g;
            int ocBl = ocAl + 8;
            float sA = g_bns[oc0 + ocAl], bA = g_bnb[oc0 + ocAl];
            float sB = g_bns[oc0 + ocBl], bB = g_bnb[oc0 + ocBl];
#pragma unroll
            for (int ni = 0; ni < 4; ni++) {
                int nnl = wn * 32 + ni * 8 + t4 * 2;
                float v0 = fmaxf(fmaf(C[mi][ni][0], sA, bA), 0.f);
                float v1 = fmaxf(fmaf(C[mi][ni][1], sA, bA), 0.f);
                float v2 = fmaxf(fmaf(C[mi][ni][2], sB, bB), 0.f);
                float v3 = fmaxf(fmaf(C[mi][ni][3], sB, bB), 0.f);
                smT[nnl * 132 + ocAl] = pack_hl(v0);
                smT[(nnl + 1) * 132 + ocAl] = pack_hl(v1);
                smT[nnl * 132 + ocBl] = pack_hl(v2);
                smT[(nnl + 1) * 132 + ocBl] = pack_hl(v3);
            }
        }
        __syncthreads();
        __nv_bfloat16* hh = g_hh + (size_t)n * PLANE_N;
        __nv_bfloat16* hl = g_hl + (size_t)n * PLANE_N;
        for (int e = tid; e < 16384; e += 256) {
            int pl = e >> 7, cl = e & 127;
            uint32_t u = smT[pl * 132 + cl];
            int srow = (ybase + (pl >> 5) + 1) * 34 + (pl & 31) + 1;
            size_t off = (size_t)srow * CHN + oc0 + cl;
            hh[off] = __ushort_as_bfloat16((unsigned short)(u & 0xffffu));
            hl[off] = __ushort_as_bfloat16((unsigned short)(u >> 16));
        }
    } else {
        float* outN = out_ext + (size_t)n * CHN * HWP;
#pragma unroll
        for (int mi = 0; mi < 4; mi++) {
            int ocA = oc0 + wm * 64 + mi * 16 + g;
            int ocB = ocA + 8;
#pragma unroll
            for (int ni = 0; ni < 4; ni++) {
                int nn = p0 + wn * 32 + ni * 8 + t4 * 2;
                *reinterpret_cast<float2*>(&outN[(size_t)ocA * HWP + nn]) =
                    make_float2(C[mi][ni][0], C[mi][ni][1]);
                *reinterpret_cast<float2*>(&outN[(size_t)ocB * HWP + nn]) =
                    make_float2(C[mi][ni][2], C[mi][ni][3]);
            }
        }
    }
}

// ======================= assign + softmax (split-K x2) =====================
__global__ void __launch_bounds__(256)
assign_softmax_kernel(const float* __restrict__ xenc, const float* __restrict__ wa) {
    __shared__ float s_w[2][8][64];
    __shared__ float s_part[128][65];
    const int n = blockIdx.x >> 3;
    const int l0 = (blockIdx.x & 7) * 128;
    const int tid = threadIdx.x;
    const int grp = tid >> 7;
    const int lt = tid & 127;
    const int l = l0 + lt;
    const int cbase = grp * 256;
    const float* xN = xenc + (size_t)n * CHN * HWP;

    float s[64];
#pragma unroll
    for (int k = 0; k < 64; k++) s[k] = 0.f;
    float ss = 0.f;

    for (int c0 = 0; c0 < 256; c0 += 8) {
#pragma unroll
        for (int r = 0; r < 4; r++) {
            int idx = lt + r * 128;
            int cc = idx >> 6, k = idx & 63;
            s_w[grp][cc][k] = wa[k * 512 + cbase + c0 + cc];
        }
        __syncthreads();
#pragma unroll
        for (int cc = 0; cc < 8; cc++) {
            float xv = xN[(cbase + c0 + cc) * HWP + l];
            ss = fmaf(xv, xv, ss);
#pragma unroll
            for (int k = 0; k < 64; k++) s[k] = fmaf(xv, s_w[grp][cc][k], s[k]);
        }
        __syncthreads();
    }

    if (grp == 1) {
#pragma unroll
        for (int k = 0; k < 64; k++) s_part[lt][k] = s[k];
        s_part[lt][64] = ss;
    }
    __syncthreads();
    if (grp == 0) {
#pragma unroll
        for (int k = 0; k < 64; k++) s[k] += s_part[lt][k];
        ss += s_part[lt][64];

        float invn = 1.f / fmaxf(sqrtf(ss), 1e-12f);
        g_invn[n * HWP + l] = invn;

        float mx = -1e30f;
#pragma unroll
        for (int k = 0; k < 64; k++) { s[k] *= invn; mx = fmaxf(mx, s[k]); }
        float sum = 0.f;
#pragma unroll
        for (int k = 0; k < 64; k++) { s[k] = expf(s[k] - mx); sum += s[k]; }
        float rs = 1.f / sum;
#pragma unroll
        for (int k = 0; k < 64; k++)
            g_sa[((size_t)n * 64 + k) * HWP + l] = s[k] * rs;
    }
}

// ======================= ssum =======================
__global__ void ssum_kernel() {
    int row = blockIdx.x;
    int tid = threadIdx.x;
    const float4* p = reinterpret_cast<const float4*>(g_sa + (size_t)row * HWP);
    float4 v = p[tid];
    float t = v.x + v.y + v.z + v.w;
    __shared__ float red[256];
    red[tid] = t;
    __syncthreads();
    for (int s = 128; s > 0; s >>= 1) {
        if (tid < s) red[tid] += red[tid + s];
        __syncthreads();
    }
    if (tid == 0) g_ssum[row] = red[0];
}

// ======================= VLAD =======================
__global__ void __launch_bounds__(256)
vlad_kernel(const float* __restrict__ xenc, const float* __restrict__ cent) {
    __shared__ float s_sa[8][1024];
    __shared__ float s_in[1024];
    const int n = blockIdx.x >> 3;
    const int k0 = (blockIdx.x & 7) * 8;
    const int tid = threadIdx.x;

    for (int i = tid; i < 1024; i += 256) s_in[i] = g_invn[n * HWP + i];
    for (int i = tid; i < 8192; i += 256) {
        int kk = i >> 10, l = i & 1023;
        s_sa[kk][l] = g_sa[((size_t)n * 64 + k0 + kk) * HWP + l];
    }
    __syncthreads();

    const int warp = tid >> 5, lane = tid & 31;
    const float* xN = xenc + (size_t)n * CHN * HWP;

    for (int c = warp; c < 512; c += 8) {
        float acc[8];
#pragma unroll
        for (int kk = 0; kk < 8; kk++) acc[kk] = 0.f;
        for (int l = lane; l < 1024; l += 32) {
            float xv = xN[c * HWP + l] * s_in[l];
#pragma unroll
            for (int kk = 0; kk < 8; kk++) acc[kk] = fmaf(xv, s_sa[kk][l], acc[kk]);
        }
#pragma unroll
        for (int kk = 0; kk < 8; kk++) {
            float v = acc[kk];
#pragma unroll
            for (int o = 16; o > 0; o >>= 1) v += __shfl_down_sync(0xffffffffu, v, o);
            if (lane == 0) {
                int k = k0 + kk;
                g_vlad[((size_t)n * 64 + k) * 512 + c] =
                    v - g_ssum[n * 64 + k] * cent[k * 512 + c];
            }
        }
    }
}

// ======================= intra norm =======================
__global__ void intra_kernel(float* __restrict__ out_vlad) {
    int row = blockIdx.x;
    int tid = threadIdx.x;
    const float2* p = reinterpret_cast<const float2*>(g_vlad + (size_t)row * 512);
    float2 v = p[tid];
    float ssq = v.x * v.x + v.y * v.y;
    __shared__ float red[256];
    red[tid] = ssq;
    __syncthreads();
    for (int s = 128; s > 0; s >>= 1) {
        if (tid < s) red[tid] += red[tid + s];
        __syncthreads();
    }
    float ss = red[0];
    float inv = 1.f / fmaxf(sqrtf(ss), 1e-12f);
    float2* o = reinterpret_cast<float2*>(out_vlad + (size_t)row * 512);
    float2 w;
    w.x = v.x * inv;
    w.y = v.y * inv;
    o[tid] = w;
    if (tid == 0) g_rowss[row] = ss * inv * inv;
}

// ======================= global scale =======================
__global__ void gscale_kernel(float* __restrict__ out_vlad) {
    int n = blockIdx.x;
    int tid = threadIdx.x;
    __shared__ float red[64];
    __shared__ float gsc;
    if (tid < 64) red[tid] = g_rowss[n * 64 + tid];
    __syncthreads();
    if (tid == 0) {
        float t = 0.f;
        for (int i = 0; i < 64; i++) t += red[i];
        gsc = 1.f / fmaxf(sqrtf(t), 1e-12f);
    }
    __syncthreads();
    float g = gsc;
    float* o = out_vlad + (size_t)n * (KCL * CHN);
    for (int i = tid; i < KCL * CHN; i += 256) o[i] *= g;
}

// ======================= launcher =======================
extern "C" void kernel_launch(void* const* d_in, const int* in_sizes, int n_in,
                              void* d_out, int out_size) {
    const float* x     = (const float*)d_in[0];
    const float* w1    = (const float*)d_in[1];
    const float* gamma = (const float*)d_in[2];
    const float* beta  = (const float*)d_in[3];
    const float* mean  = (const float*)d_in[4];
    const float* var   = (const float*)d_in[5];
    const float* w2    = (const float*)d_in[6];
    const float* wa    = (const float*)d_in[7];
    const float* cent  = (const float*)d_in[8];

    float* out = (float*)d_out;
    float* out_vlad = out;
    float* out_xenc = out + (size_t)N_IMG * KCL * CHN;

    static int smem_set = 0;
    if (!smem_set) {
        cudaFuncSetAttribute(conv_mma_kernel,
                             cudaFuncAttributeMaxDynamicSharedMemorySize,
                             CONV_DSMEM);
        smem_set = 1;
    }

    prep_kernel<<<18432, 256>>>(w1, w2, gamma, beta, mean, var);
    dim3 pgrid(16, 32, N_IMG);
    pack_x_kernel<<<pgrid, 256>>>(x);

    dim3 cgrid(8, 4, N_IMG);
    conv_mma_kernel<<<cgrid, 256, CONV_DSMEM>>>(nullptr, 1);
    conv_mma_kernel<<<cgrid, 256, CONV_DSMEM>>>(out_xenc, 2);

    assign_softmax_kernel<<<N_IMG * 8, 256>>>(out_xenc, wa);
    ssum_kernel<<<N_IMG * KCL, 256>>>();
    vlad_kernel<<<N_IMG * 8, 256>>>(out_xenc, cent);
    intra_kernel<<<N_IMG * KCL, 256>>>(out_vlad);
    gscale_kernel<<<N_IMG, 256>>>(out_vlad);
}

// round 8
// speedup vs baseline: 1.6495x; 1.6495x over previous
#include <cuda_runtime.h>
#include <cuda_bf16.h>
#include <cstdint>

// ---------------------------------------------------------------------------
// NetVLAD on GB300 — round 7: Winograd F(2x2,3x3) convs. 16 t-batched GEMMs
// (M=512 oc, N=4096 tiles, K=512 ic) with bf16x3 mma.sync; fp32 transforms.
// ---------------------------------------------------------------------------

#define N_IMG   16
#define CHN     512
#define HWP     1024
#define KCL     64
#define NTILE   4096          // 16 img * 256 tiles
#define AP      40            // SMEM row pitch in bf16 (80B)
#define PPOS    1156          // 34*34 padded positions
#define PLANE_N (PPOS * CHN)

// GEMM stage layout (bytes): Ah 0, Al 10240, Bh 20480, Bl 30720
#define STAGE_BYTES 40960
#define OFF_AL 10240
#define OFF_BH 20480
#define OFF_BL 30720
#define GEMM_DSMEM (2 * STAGE_BYTES)
#define NCHUNK 16             // K=512 / 32

// -------- device scratch --------
__device__ __align__(16) __nv_bfloat16 g_U1h[16 * CHN * CHN];
__device__ __align__(16) __nv_bfloat16 g_U1l[16 * CHN * CHN];
__device__ __align__(16) __nv_bfloat16 g_U2h[16 * CHN * CHN];
__device__ __align__(16) __nv_bfloat16 g_U2l[16 * CHN * CHN];
__device__ __align__(16) __nv_bfloat16 g_Vh[16 * NTILE * CHN];
__device__ __align__(16) __nv_bfloat16 g_Vl[16 * NTILE * CHN];
__device__ __align__(16) float g_M[(size_t)16 * NTILE * CHN];
// conv1 output planes, halo-padded transposed: [n][(y+1)*34+(x+1)][c]
__device__ __align__(16) __nv_bfloat16 g_hh[N_IMG * PLANE_N];
__device__ __align__(16) __nv_bfloat16 g_hl[N_IMG * PLANE_N];
__device__ float g_invn[N_IMG * HWP];
__device__ float g_sa[N_IMG * KCL * HWP];
__device__ float g_ssum[N_IMG * KCL];
__device__ float g_vlad[N_IMG * KCL * CHN];
__device__ float g_rowss[N_IMG * KCL];
__device__ float g_bns[CHN];
__device__ float g_bnb[CHN];

// -------- helpers --------
__device__ __forceinline__ uint32_t smem_u32(const void* p) {
    uint32_t a;
    asm("{ .reg .u64 t; cvta.to.shared.u64 t, %1; cvt.u32.u64 %0, t; }"
        : "=r"(a) : "l"(p));
    return a;
}
__device__ __forceinline__ void ldm_x4(uint32_t r[4], uint32_t addr) {
    asm volatile("ldmatrix.sync.aligned.m8n8.x4.shared.b16 {%0,%1,%2,%3}, [%4];"
                 : "=r"(r[0]), "=r"(r[1]), "=r"(r[2]), "=r"(r[3]) : "r"(addr));
}
__device__ __forceinline__ void mma_bf16(float c[4], const uint32_t a[4],
                                         uint32_t b0, uint32_t b1) {
    asm volatile(
        "mma.sync.aligned.m16n8k16.row.col.f32.bf16.bf16.f32 "
        "{%0,%1,%2,%3}, {%4,%5,%6,%7}, {%8,%9}, {%0,%1,%2,%3};"
        : "+f"(c[0]), "+f"(c[1]), "+f"(c[2]), "+f"(c[3])
        : "r"(a[0]), "r"(a[1]), "r"(a[2]), "r"(a[3]), "r"(b0), "r"(b1));
}
__device__ __forceinline__ void cp_async16(uint32_t dst, const void* src) {
    asm volatile("cp.async.cg.shared.global [%0], [%1], 16;"
                 :: "r"(dst), "l"(src));
}
#define CP_COMMIT() asm volatile("cp.async.commit_group;" ::: "memory")
#define CP_WAIT(n)  asm volatile("cp.async.wait_group %0;" :: "n"(n) : "memory")

// ======================= prep: Winograd weight transform + BN fold =========
// U = G g G^T per (oc,ic); split hi/lo; layout U[t][oc][ic].
__global__ void __launch_bounds__(256)
prep_wino_kernel(const float* __restrict__ w1, const float* __restrict__ w2,
                 const float* __restrict__ gamma, const float* __restrict__ beta,
                 const float* __restrict__ mean, const float* __restrict__ var) {
    int idx = blockIdx.x * 256 + threadIdx.x;
    const int per = CHN * CHN;           // 262144
    if (idx < 2 * per) {
        int which = (idx >= per) ? 1 : 0;
        int r = idx - which * per;
        int oc = r >> 9;
        int ic = r & 511;
        const float* w = (which ? w2 : w1) + (size_t)oc * 4608 + ic * 9;
        float g[9];
#pragma unroll
        for (int k = 0; k < 9; k++) g[k] = w[k];
        float a[4][3];
#pragma unroll
        for (int c = 0; c < 3; c++) {
            a[0][c] = g[c];
            a[1][c] = (g[c] + g[3 + c] + g[6 + c]) * 0.5f;
            a[2][c] = (g[c] - g[3 + c] + g[6 + c]) * 0.5f;
            a[3][c] = g[6 + c];
        }
        __nv_bfloat16* Uh = which ? g_U2h : g_U1h;
        __nv_bfloat16* Ul = which ? g_U2l : g_U1l;
#pragma unroll
        for (int i = 0; i < 4; i++) {
            float u0 = a[i][0];
            float u1 = (a[i][0] + a[i][1] + a[i][2]) * 0.5f;
            float u2 = (a[i][0] - a[i][1] + a[i][2]) * 0.5f;
            float u3 = a[i][2];
            float uv[4] = {u0, u1, u2, u3};
#pragma unroll
            for (int j = 0; j < 4; j++) {
                int t = i * 4 + j;
                size_t off = ((size_t)t * CHN + oc) * CHN + ic;
                float v = uv[j];
                __nv_bfloat16 h = __float2bfloat16(v);
                __nv_bfloat16 l = __float2bfloat16(v - __bfloat162float(h));
                Uh[off] = h;
                Ul[off] = l;
            }
        }
    }
    if (idx < CHN) {
        float inv = rsqrtf(var[idx] + 1e-5f);
        float s = gamma[idx] * inv;
        g_bns[idx] = s;
        g_bnb[idx] = beta[idx] - mean[idx] * s;
    }
}

// ======================= input transform =======================
// V = B^T d B per (tile, c); layout V[t][gtile][c] hi/lo.
// which==1: source x fp32 NCHW. which==2: source h planes (hi+lo).
// grid (16 cb, 16 ty, 16 n), block 256.
__global__ void __launch_bounds__(256)
inx_kernel(const float* __restrict__ x, int which) {
    __shared__ float s_in[32 * 136];      // [c][rr][col], 4x34 per c
    const int cb = blockIdx.x, ty = blockIdx.y, n = blockIdx.z;
    const int tid = threadIdx.x;

    if (which == 1) {
        const float* xN = x + ((size_t)n * CHN + cb * 32) * HWP;
        for (int i = tid; i < 4352; i += 256) {
            int c = i / 136;
            int rem = i - c * 136;
            int rr = rem / 34;
            int col = rem - rr * 34;
            int gy = 2 * ty - 1 + rr;
            int gx = col - 1;
            float v = 0.f;
            if ((unsigned)gy < 32u && (unsigned)gx < 32u)
                v = xN[(size_t)c * HWP + gy * 32 + gx];
            s_in[c * 136 + rr * 34 + col] = v;
        }
    } else {
        const __nv_bfloat16* hh = g_hh + (size_t)n * PLANE_N + cb * 32;
        const __nv_bfloat16* hl = g_hl + (size_t)n * PLANE_N + cb * 32;
        for (int i = tid; i < 4352; i += 256) {
            int c = i & 31;
            int j = i >> 5;              // 0..135
            int rr = j / 34;
            int col = j - rr * 34;
            size_t off = (size_t)((2 * ty + rr) * 34 + col) * CHN + c;
            float v = __bfloat162float(hh[off]) + __bfloat162float(hl[off]);
            s_in[c * 136 + rr * 34 + col] = v;
        }
    }
    __syncthreads();

#pragma unroll
    for (int it = 0; it < 2; it++) {
        int item = tid + it * 256;       // 512 items
        int c = item & 31;
        int tx = item >> 5;
        const float* dd = &s_in[c * 136];
        float d[4][4];
#pragma unroll
        for (int r = 0; r < 4; r++)
#pragma unroll
            for (int cc = 0; cc < 4; cc++)
                d[r][cc] = dd[r * 34 + 2 * tx + cc];
        float p[4][4];
#pragma unroll
        for (int cc = 0; cc < 4; cc++) {
            p[0][cc] = d[0][cc] - d[2][cc];
            p[1][cc] = d[1][cc] + d[2][cc];
            p[2][cc] = d[2][cc] - d[1][cc];
            p[3][cc] = d[1][cc] - d[3][cc];
        }
        int gtile = n * 256 + ty * 16 + tx;
        int ch = cb * 32 + c;
#pragma unroll
        for (int r = 0; r < 4; r++) {
            float v0 = p[r][0] - p[r][2];
            float v1 = p[r][1] + p[r][2];
            float v2 = p[r][2] - p[r][1];
            float v3 = p[r][1] - p[r][3];
            float vv[4] = {v0, v1, v2, v3};
#pragma unroll
            for (int j = 0; j < 4; j++) {
                int t = r * 4 + j;
                size_t off = ((size_t)t * NTILE + gtile) * CHN + ch;
                float v = vv[j];
                __nv_bfloat16 h = __float2bfloat16(v);
                __nv_bfloat16 l = __float2bfloat16(v - __bfloat162float(h));
                g_Vh[off] = h;
                g_Vl[off] = l;
            }
        }
    }
}

// ======================= Winograd GEMM (bf16x3 mma.sync) ===================
// C[oc 128][tile 128] = U_t[128, 512] * V_t[128, 512]^T, per (nt, ot, t).
// Epilogue: transpose via smem -> g_M[t][tile][oc] fp32.
__global__ void __launch_bounds__(256, 2)
gemm_wino_kernel(int which) {
    extern __shared__ __align__(16) char dynsm[];
    const uint32_t smbase = smem_u32(dynsm);

    const int tid = threadIdx.x;
    const int lane = tid & 31, warp = tid >> 5;
    const int wm = warp >> 2, wn = warp & 3;
    const int nt0 = blockIdx.x * 128;
    const int oc0 = blockIdx.y * 128;
    const int t = blockIdx.z;

    const __nv_bfloat16* Uh = (which == 1) ? g_U1h : g_U2h;
    const __nv_bfloat16* Ul = (which == 1) ? g_U1l : g_U2l;

    const int frow = tid >> 1, fhalf = tid & 1;

    const int lt = lane >> 3, lr = lane & 7;
    const int a_row_off = (lt & 1) * 8 + lr;
    const int a_col_off = (lt >> 1) * 8;
    const int b_row_off = (lt >> 1) * 8 + lr;
    const int b_col_off = (lt & 1) * 8;

    float C[4][4][4];
#pragma unroll
    for (int mi = 0; mi < 4; mi++)
#pragma unroll
        for (int ni = 0; ni < 4; ni++)
#pragma unroll
            for (int q = 0; q < 4; q++) C[mi][ni][q] = 0.f;

    auto fill = [&](int chunk, int stage) {
        const int k0 = chunk << 5;
        const uint32_t sb = smbase + stage * STAGE_BYTES;
        {
            size_t o = ((size_t)t * CHN + oc0 + frow) * CHN + k0 + fhalf * 16;
            uint32_t d = sb + frow * 80 + fhalf * 32;
            cp_async16(d, Uh + o);
            cp_async16(d + 16, Uh + o + 8);
            cp_async16(d + OFF_AL, Ul + o);
            cp_async16(d + OFF_AL + 16, Ul + o + 8);
        }
        {
            size_t o = ((size_t)t * NTILE + nt0 + frow) * CHN + k0 + fhalf * 16;
            uint32_t d = sb + frow * 80 + fhalf * 32;
            cp_async16(d + OFF_BH, g_Vh + o);
            cp_async16(d + OFF_BH + 16, g_Vh + o + 8);
            cp_async16(d + OFF_BL, g_Vl + o);
            cp_async16(d + OFF_BL + 16, g_Vl + o + 8);
        }
    };

    fill(0, 0); CP_COMMIT();
    fill(1, 1); CP_COMMIT();

    for (int chunk = 0; chunk < NCHUNK; ++chunk) {
        const int stage = chunk & 1;
        if (chunk == NCHUNK - 1) { CP_WAIT(0); } else { CP_WAIT(1); }
        __syncthreads();

        const uint32_t sb = smbase + stage * STAGE_BYTES;
#pragma unroll
        for (int s = 0; s < 2; ++s) {
            const int kk0 = s * 16;
            uint32_t Af[4][4], Bhf[2][4], Blf[2][4];
#pragma unroll
            for (int mi = 0; mi < 4; mi++) {
                int row = wm * 64 + mi * 16 + a_row_off;
                ldm_x4(Af[mi], sb + (uint32_t)(row * AP + kk0 + a_col_off) * 2);
            }
#pragma unroll
            for (int g = 0; g < 2; g++) {
                int row = wn * 32 + g * 16 + b_row_off;
                uint32_t off = (uint32_t)(row * AP + kk0 + b_col_off) * 2;
                ldm_x4(Bhf[g], sb + OFF_BH + off);
                ldm_x4(Blf[g], sb + OFF_BL + off);
            }
#pragma unroll
            for (int mi = 0; mi < 4; mi++)
#pragma unroll
                for (int ni = 0; ni < 4; ni++)
                    mma_bf16(C[mi][ni], Af[mi],
                             Bhf[ni >> 1][(ni & 1) * 2],
                             Bhf[ni >> 1][(ni & 1) * 2 + 1]);
#pragma unroll
            for (int mi = 0; mi < 4; mi++)
#pragma unroll
                for (int ni = 0; ni < 4; ni++)
                    mma_bf16(C[mi][ni], Af[mi],
                             Blf[ni >> 1][(ni & 1) * 2],
                             Blf[ni >> 1][(ni & 1) * 2 + 1]);
#pragma unroll
            for (int mi = 0; mi < 4; mi++) {
                int row = wm * 64 + mi * 16 + a_row_off;
                ldm_x4(Af[mi],
                       sb + OFF_AL + (uint32_t)(row * AP + kk0 + a_col_off) * 2);
            }
#pragma unroll
            for (int mi = 0; mi < 4; mi++)
#pragma unroll
                for (int ni = 0; ni < 4; ni++)
                    mma_bf16(C[mi][ni], Af[mi],
                             Bhf[ni >> 1][(ni & 1) * 2],
                             Bhf[ni >> 1][(ni & 1) * 2 + 1]);
        }

        if (chunk + 2 < NCHUNK) {
            __syncthreads();
            fill(chunk + 2, stage);
            CP_COMMIT();
        }
    }

    // epilogue: transpose through smem -> g_M[t][tile][oc]
    __syncthreads();
    float* sC = reinterpret_cast<float*>(dynsm);       // pitch 132
    const int g = lane >> 2, t4 = lane & 3;
#pragma unroll
    for (int mi = 0; mi < 4; mi++) {
        int ocA = wm * 64 + mi * 16 + g;
        int ocB = ocA + 8;
#pragma unroll
        for (int ni = 0; ni < 4; ni++) {
            int nn = wn * 32 + ni * 8 + t4 * 2;
            sC[nn * 132 + ocA] = C[mi][ni][0];
            sC[(nn + 1) * 132 + ocA] = C[mi][ni][1];
            sC[nn * 132 + ocB] = C[mi][ni][2];
            sC[(nn + 1) * 132 + ocB] = C[mi][ni][3];
        }
    }
    __syncthreads();
    float* Mo = g_M + ((size_t)t * NTILE + nt0) * CHN + oc0;
    for (int e = tid; e < 16384; e += 256) {
        int tl = e >> 7, ocl = e & 127;
        Mo[(size_t)tl * CHN + ocl] = sC[tl * 132 + ocl];
    }
}

// ======================= output transform, conv1 ===========================
// y = A^T M A; BN+ReLU; split hi/lo; write h planes [pos][c].
// grid (4 ocq, 16 ty, 16 n), block 256, 8 iters.
__global__ void __launch_bounds__(256)
outx1_kernel() {
    const int ocq = blockIdx.x, ty = blockIdx.y, n = blockIdx.z;
    const int tid = threadIdx.x;
    __nv_bfloat16* hh = g_hh + (size_t)n * PLANE_N;
    __nv_bfloat16* hl = g_hl + (size_t)n * PLANE_N;
#pragma unroll
    for (int it = 0; it < 8; it++) {
        int item = tid + it * 256;       // 2048 = 16 tx * 128 oc
        int oc = ocq * 128 + (item & 127);
        int tx = item >> 7;
        int gtile = n * 256 + ty * 16 + tx;
        float m[16];
#pragma unroll
        for (int t = 0; t < 16; t++)
            m[t] = g_M[((size_t)t * NTILE + gtile) * CHN + oc];
        float tmp[2][4];
#pragma unroll
        for (int j = 0; j < 4; j++) {
            tmp[0][j] = m[j] + m[4 + j] + m[8 + j];
            tmp[1][j] = m[4 + j] - m[8 + j] - m[12 + j];
        }
        float s = g_bns[oc], b = g_bnb[oc];
#pragma unroll
        for (int i = 0; i < 2; i++) {
            float y0 = tmp[i][0] + tmp[i][1] + tmp[i][2];
            float y1 = tmp[i][1] - tmp[i][2] - tmp[i][3];
            float yv[2] = {y0, y1};
#pragma unroll
            for (int j = 0; j < 2; j++) {
                float v = fmaxf(fmaf(yv[j], s, b), 0.f);
                __nv_bfloat16 h = __float2bfloat16(v);
                __nv_bfloat16 l = __float2bfloat16(v - __bfloat162float(h));
                int pos = (2 * ty + i + 1) * 34 + (2 * tx + j + 1);
                size_t off = (size_t)pos * CHN + oc;
                hh[off] = h;
                hl[off] = l;
            }
        }
    }
}

// ======================= output transform, conv2 -> x_enc fp32 =============
// grid (4 ocq, 16 ty, 16 n), block 256; smem transpose for coalesced writes.
__global__ void __launch_bounds__(256)
outx2_kernel(float* __restrict__ out) {
    __shared__ float sO[128][67];        // [oc_l][yy*33 + col]
    const int ocq = blockIdx.x, ty = blockIdx.y, n = blockIdx.z;
    const int tid = threadIdx.x;
#pragma unroll
    for (int it = 0; it < 8; it++) {
        int item = tid + it * 256;
        int ocl = item & 127;
        int tx = item >> 7;
        int oc = ocq * 128 + ocl;
        int gtile = n * 256 + ty * 16 + tx;
        float m[16];
#pragma unroll
        for (int t = 0; t < 16; t++)
            m[t] = g_M[((size_t)t * NTILE + gtile) * CHN + oc];
        float tmp[2][4];
#pragma unroll
        for (int j = 0; j < 4; j++) {
            tmp[0][j] = m[j] + m[4 + j] + m[8 + j];
            tmp[1][j] = m[4 + j] - m[8 + j] - m[12 + j];
        }
#pragma unroll
        for (int i = 0; i < 2; i++) {
            float y0 = tmp[i][0] + tmp[i][1] + tmp[i][2];
            float y1 = tmp[i][1] - tmp[i][2] - tmp[i][3];
            sO[ocl][i * 33 + 2 * tx] = y0;
            sO[ocl][i * 33 + 2 * tx + 1] = y1;
        }
    }
    __syncthreads();
    float* oN = out + ((size_t)n * CHN + ocq * 128) * HWP;
    for (int e = tid; e < 8192; e += 256) {
        int ocl = e >> 6;
        int r2 = e & 63;
        int yy = r2 >> 5, col = r2 & 31;
        oN[(size_t)ocl * HWP + (2 * ty + yy) * 32 + col] = sO[ocl][yy * 33 + col];
    }
}

// ======================= assign + softmax (split-K x2) =====================
__global__ void __launch_bounds__(256)
assign_softmax_kernel(const float* __restrict__ xenc, const float* __restrict__ wa) {
    __shared__ float s_w[2][8][64];
    __shared__ float s_part[128][65];
    const int n = blockIdx.x >> 3;
    const int l0 = (blockIdx.x & 7) * 128;
    const int tid = threadIdx.x;
    const int grp = tid >> 7;
    const int lt = tid & 127;
    const int l = l0 + lt;
    const int cbase = grp * 256;
    const float* xN = xenc + (size_t)n * CHN * HWP;

    float s[64];
#pragma unroll
    for (int k = 0; k < 64; k++) s[k] = 0.f;
    float ss = 0.f;

    for (int c0 = 0; c0 < 256; c0 += 8) {
#pragma unroll
        for (int r = 0; r < 4; r++) {
            int idx = lt + r * 128;
            int cc = idx >> 6, k = idx & 63;
            s_w[grp][cc][k] = wa[k * 512 + cbase + c0 + cc];
        }
        __syncthreads();
#pragma unroll
        for (int cc = 0; cc < 8; cc++) {
            float xv = xN[(cbase + c0 + cc) * HWP + l];
            ss = fmaf(xv, xv, ss);
#pragma unroll
            for (int k = 0; k < 64; k++) s[k] = fmaf(xv, s_w[grp][cc][k], s[k]);
        }
        __syncthreads();
    }

    if (grp == 1) {
#pragma unroll
        for (int k = 0; k < 64; k++) s_part[lt][k] = s[k];
        s_part[lt][64] = ss;
    }
    __syncthreads();
    if (grp == 0) {
#pragma unroll
        for (int k = 0; k < 64; k++) s[k] += s_part[lt][k];
        ss += s_part[lt][64];

        float invn = 1.f / fmaxf(sqrtf(ss), 1e-12f);
        g_invn[n * HWP + l] = invn;

        float mx = -1e30f;
#pragma unroll
        for (int k = 0; k < 64; k++) { s[k] *= invn; mx = fmaxf(mx, s[k]); }
        float sum = 0.f;
#pragma unroll
        for (int k = 0; k < 64; k++) { s[k] = expf(s[k] - mx); sum += s[k]; }
        float rs = 1.f / sum;
#pragma unroll
        for (int k = 0; k < 64; k++)
            g_sa[((size_t)n * 64 + k) * HWP + l] = s[k] * rs;
    }
}

// ======================= ssum =======================
__global__ void ssum_kernel() {
    int row = blockIdx.x;
    int tid = threadIdx.x;
    const float4* p = reinterpret_cast<const float4*>(g_sa + (size_t)row * HWP);
    float4 v = p[tid];
    float t = v.x + v.y + v.z + v.w;
    __shared__ float red[256];
    red[tid] = t;
    __syncthreads();
    for (int s = 128; s > 0; s >>= 1) {
        if (tid < s) red[tid] += red[tid + s];
        __syncthreads();
    }
    if (tid == 0) g_ssum[row] = red[0];
}

// ======================= VLAD =======================
__global__ void __launch_bounds__(256)
vlad_kernel(const float* __restrict__ xenc, const float* __restrict__ cent) {
    __shared__ float s_sa[8][1024];
    __shared__ float s_in[1024];
    const int n = blockIdx.x >> 3;
    const int k0 = (blockIdx.x & 7) * 8;
    const int tid = threadIdx.x;

    for (int i = tid; i < 1024; i += 256) s_in[i] = g_invn[n * HWP + i];
    for (int i = tid; i < 8192; i += 256) {
        int kk = i >> 10, l = i & 1023;
        s_sa[kk][l] = g_sa[((size_t)n * 64 + k0 + kk) * HWP + l];
    }
    __syncthreads();

    const int warp = tid >> 5, lane = tid & 31;
    const float* xN = xenc + (size_t)n * CHN * HWP;

    for (int c = warp; c < 512; c += 8) {
        float acc[8];
#pragma unroll
        for (int kk = 0; kk < 8; kk++) acc[kk] = 0.f;
        for (int l = lane; l < 1024; l += 32) {
            float xv = xN[c * HWP + l] * s_in[l];
#pragma unroll
            for (int kk = 0; kk < 8; kk++) acc[kk] = fmaf(xv, s_sa[kk][l], acc[kk]);
        }
#pragma unroll
        for (int kk = 0; kk < 8; kk++) {
            float v = acc[kk];
#pragma unroll
            for (int o = 16; o > 0; o >>= 1) v += __shfl_down_sync(0xffffffffu, v, o);
            if (lane == 0) {
                int k = k0 + kk;
                g_vlad[((size_t)n * 64 + k) * 512 + c] =
                    v - g_ssum[n * 64 + k] * cent[k * 512 + c];
            }
        }
    }
}

// ======================= intra norm =======================
__global__ void intra_kernel(float* __restrict__ out_vlad) {
    int row = blockIdx.x;
    int tid = threadIdx.x;
    const float2* p = reinterpret_cast<const float2*>(g_vlad + (size_t)row * 512);
    float2 v = p[tid];
    float ssq = v.x * v.x + v.y * v.y;
    __shared__ float red[256];
    red[tid] = ssq;
    __syncthreads();
    for (int s = 128; s > 0; s >>= 1) {
        if (tid < s) red[tid] += red[tid + s];
        __syncthreads();
    }
    float ss = red[0];
    float inv = 1.f / fmaxf(sqrtf(ss), 1e-12f);
    float2* o = reinterpret_cast<float2*>(out_vlad + (size_t)row * 512);
    float2 w;
    w.x = v.x * inv;
    w.y = v.y * inv;
    o[tid] = w;
    if (tid == 0) g_rowss[row] = ss * inv * inv;
}

// ======================= global scale =======================
__global__ void gscale_kernel(float* __restrict__ out_vlad) {
    int n = blockIdx.x;
    int tid = threadIdx.x;
    __shared__ float red[64];
    __shared__ float gsc;
    if (tid < 64) red[tid] = g_rowss[n * 64 + tid];
    __syncthreads();
    if (tid == 0) {
        float t = 0.f;
        for (int i = 0; i < 64; i++) t += red[i];
        gsc = 1.f / fmaxf(sqrtf(t), 1e-12f);
    }
    __syncthreads();
    float g = gsc;
    float* o = out_vlad + (size_t)n * (KCL * CHN);
    for (int i = tid; i < KCL * CHN; i += 256) o[i] *= g;
}

// ======================= launcher =======================
extern "C" void kernel_launch(void* const* d_in, const int* in_sizes, int n_in,
                              void* d_out, int out_size) {
    const float* x     = (const float*)d_in[0];
    const float* w1    = (const float*)d_in[1];
    const float* gamma = (const float*)d_in[2];
    const float* beta  = (const float*)d_in[3];
    const float* mean  = (const float*)d_in[4];
    const float* var   = (const float*)d_in[5];
    const float* w2    = (const float*)d_in[6];
    const float* wa    = (const float*)d_in[7];
    const float* cent  = (const float*)d_in[8];

    float* out = (float*)d_out;
    float* out_vlad = out;
    float* out_xenc = out + (size_t)N_IMG * KCL * CHN;

    static int smem_set = 0;
    if (!smem_set) {
        cudaFuncSetAttribute(gemm_wino_kernel,
                             cudaFuncAttributeMaxDynamicSharedMemorySize,
                             GEMM_DSMEM);
        smem_set = 1;
    }

    prep_wino_kernel<<<2048, 256>>>(w1, w2, gamma, beta, mean, var);

    dim3 tgrid(16, 16, N_IMG);
    dim3 ggrid(32, 4, 16);
    dim3 ogrid(4, 16, N_IMG);

    inx_kernel<<<tgrid, 256>>>(x, 1);
    gemm_wino_kernel<<<ggrid, 256, GEMM_DSMEM>>>(1);
    outx1_kernel<<<ogrid, 256>>>();

    inx_kernel<<<tgrid, 256>>>(nullptr, 2);
    gemm_wino_kernel<<<ggrid, 256, GEMM_DSMEM>>>(2);
    outx2_kernel<<<ogrid, 256>>>(out_xenc);

    assign_softmax_kernel<<<N_IMG * 8, 256>>>(out_xenc, wa);
    ssum_kernel<<<N_IMG * KCL, 256>>>();
    vlad_kernel<<<N_IMG * 8, 256>>>(out_xenc, cent);
    intra_kernel<<<N_IMG * KCL, 256>>>(out_vlad);
    gscale_kernel<<<N_IMG, 256>>>(out_vlad);
}

// round 9
// speedup vs baseline: 2.3531x; 1.4265x over previous
#include <cuda_runtime.h>
#include <cuda_bf16.h>
#include <cstdint>

// ---------------------------------------------------------------------------
// NetVLAD on GB300 — round 8: Winograd F(4x4,3x3). 36 t-batched GEMMs
// (M=512 oc, N=1024 tiles, K=512 ic) with bf16x3 mma.sync; fp32 transforms.
// ---------------------------------------------------------------------------

#define N_IMG   16
#define CHN     512
#define HWP     1024
#define KCL     64
#define NTILE   1024          // 16 img * 64 tiles (8x8 of 4x4 outputs)
#define NT      36            // 6x6 Winograd components
#define AP      40            // SMEM row pitch in bf16 (80B)
#define PPOS    1156          // 34*34 padded positions
#define PLANE_N (PPOS * CHN)

// GEMM stage layout (bytes): Ah 0, Al 10240, Bh 20480, Bl 30720
#define STAGE_BYTES 40960
#define OFF_AL 10240
#define OFF_BH 20480
#define OFF_BL 30720
#define GEMM_DSMEM (2 * STAGE_BYTES)
#define NCHUNK 16             // K=512 / 32

// -------- device scratch --------
__device__ __align__(16) __nv_bfloat16 g_U1h[NT * CHN * CHN];
__device__ __align__(16) __nv_bfloat16 g_U1l[NT * CHN * CHN];
__device__ __align__(16) __nv_bfloat16 g_U2h[NT * CHN * CHN];
__device__ __align__(16) __nv_bfloat16 g_U2l[NT * CHN * CHN];
__device__ __align__(16) __nv_bfloat16 g_Vh[NT * NTILE * CHN];
__device__ __align__(16) __nv_bfloat16 g_Vl[NT * NTILE * CHN];
__device__ __align__(16) float g_M[(size_t)NT * NTILE * CHN];
// conv1 output planes, halo-padded transposed: [n][(y+1)*34+(x+1)][c]
__device__ __align__(16) __nv_bfloat16 g_hh[N_IMG * PLANE_N];
__device__ __align__(16) __nv_bfloat16 g_hl[N_IMG * PLANE_N];
__device__ float g_invn[N_IMG * HWP];
__device__ float g_sa[N_IMG * KCL * HWP];
__device__ float g_ssum[N_IMG * KCL];
__device__ float g_vlad[N_IMG * KCL * CHN];
__device__ float g_rowss[N_IMG * KCL];
__device__ float g_bns[CHN];
__device__ float g_bnb[CHN];

// -------- helpers --------
__device__ __forceinline__ uint32_t smem_u32(const void* p) {
    uint32_t a;
    asm("{ .reg .u64 t; cvta.to.shared.u64 t, %1; cvt.u32.u64 %0, t; }"
        : "=r"(a) : "l"(p));
    return a;
}
__device__ __forceinline__ void ldm_x4(uint32_t r[4], uint32_t addr) {
    asm volatile("ldmatrix.sync.aligned.m8n8.x4.shared.b16 {%0,%1,%2,%3}, [%4];"
                 : "=r"(r[0]), "=r"(r[1]), "=r"(r[2]), "=r"(r[3]) : "r"(addr));
}
__device__ __forceinline__ void mma_bf16(float c[4], const uint32_t a[4],
                                         uint32_t b0, uint32_t b1) {
    asm volatile(
        "mma.sync.aligned.m16n8k16.row.col.f32.bf16.bf16.f32 "
        "{%0,%1,%2,%3}, {%4,%5,%6,%7}, {%8,%9}, {%0,%1,%2,%3};"
        : "+f"(c[0]), "+f"(c[1]), "+f"(c[2]), "+f"(c[3])
        : "r"(a[0]), "r"(a[1]), "r"(a[2]), "r"(a[3]), "r"(b0), "r"(b1));
}
__device__ __forceinline__ void cp_async16(uint32_t dst, const void* src) {
    asm volatile("cp.async.cg.shared.global [%0], [%1], 16;"
                 :: "r"(dst), "l"(src));
}
#define CP_COMMIT() asm volatile("cp.async.commit_group;" ::: "memory")
#define CP_WAIT(n)  asm volatile("cp.async.wait_group %0;" :: "n"(n) : "memory")

__device__ __forceinline__ void split_store(__nv_bfloat16* ph, __nv_bfloat16* pl,
                                            size_t off, float v) {
    __nv_bfloat16 h = __float2bfloat16(v);
    ph[off] = h;
    pl[off] = __float2bfloat16(v - __bfloat162float(h));
}

// ======================= prep: F(4,3) weight transform + BN fold ===========
// U = G g G^T; layout U[t][oc][ic] hi/lo.
__global__ void __launch_bounds__(256)
prep_wino_kernel(const float* __restrict__ w1, const float* __restrict__ w2,
                 const float* __restrict__ gamma, const float* __restrict__ beta,
                 const float* __restrict__ mean, const float* __restrict__ var) {
    int idx = blockIdx.x * 256 + threadIdx.x;
    const int per = CHN * CHN;
    if (idx < 2 * per) {
        int which = (idx >= per) ? 1 : 0;
        int r = idx - which * per;
        int oc = r >> 9;
        int ic = r & 511;
        const float* w = (which ? w2 : w1) + (size_t)oc * 4608 + ic * 9;
        float g[3][3];
#pragma unroll
        for (int i = 0; i < 3; i++)
#pragma unroll
            for (int j = 0; j < 3; j++) g[i][j] = w[i * 3 + j];
        // a = G g  (6x3)
        float a[6][3];
#pragma unroll
        for (int c = 0; c < 3; c++) {
            float g0 = g[0][c], g1 = g[1][c], g2 = g[2][c];
            a[0][c] = 0.25f * g0;
            a[1][c] = (-1.f / 6.f) * (g0 + g1 + g2);
            a[2][c] = (-1.f / 6.f) * (g0 - g1 + g2);
            a[3][c] = (1.f / 24.f) * g0 + (1.f / 12.f) * g1 + (1.f / 6.f) * g2;
            a[4][c] = (1.f / 24.f) * g0 - (1.f / 12.f) * g1 + (1.f / 6.f) * g2;
            a[5][c] = g2;
        }
        __nv_bfloat16* Uh = which ? g_U2h : g_U1h;
        __nv_bfloat16* Ul = which ? g_U2l : g_U1l;
#pragma unroll
        for (int i = 0; i < 6; i++) {
            float b0 = a[i][0], b1 = a[i][1], b2 = a[i][2];
            float u[6];
            u[0] = 0.25f * b0;
            u[1] = (-1.f / 6.f) * (b0 + b1 + b2);
            u[2] = (-1.f / 6.f) * (b0 - b1 + b2);
            u[3] = (1.f / 24.f) * b0 + (1.f / 12.f) * b1 + (1.f / 6.f) * b2;
            u[4] = (1.f / 24.f) * b0 - (1.f / 12.f) * b1 + (1.f / 6.f) * b2;
            u[5] = b2;
#pragma unroll
            for (int j = 0; j < 6; j++) {
                int t = i * 6 + j;
                size_t off = ((size_t)t * CHN + oc) * CHN + ic;
                split_store(Uh, Ul, off, u[j]);
            }
        }
    }
    if (idx < CHN) {
        float inv = rsqrtf(var[idx] + 1e-5f);
        float s = gamma[idx] * inv;
        g_bns[idx] = s;
        g_bnb[idx] = beta[idx] - mean[idx] * s;
    }
}

// ======================= input transform: V = B^T d B =======================
// grid (16 cb, 8 ty, 16 n), block 256. Strip: 32 c x 6 rows x 34 cols.
__global__ void __launch_bounds__(256)
inx_kernel(const float* __restrict__ x, int which) {
    __shared__ float s_in[32 * 204];      // [c][rr*34+col]
    const int cb = blockIdx.x, ty = blockIdx.y, n = blockIdx.z;
    const int tid = threadIdx.x;

    if (which == 1) {
        const float* xN = x + ((size_t)n * CHN + cb * 32) * HWP;
        for (int i = tid; i < 6528; i += 256) {
            int c = i / 204;
            int rem = i - c * 204;
            int rr = rem / 34;
            int col = rem - rr * 34;
            int gy = 4 * ty - 1 + rr;
            int gx = col - 1;
            float v = 0.f;
            if ((unsigned)gy < 32u && (unsigned)gx < 32u)
                v = xN[(size_t)c * HWP + gy * 32 + gx];
            s_in[c * 204 + rr * 34 + col] = v;
        }
    } else {
        const __nv_bfloat16* hh = g_hh + (size_t)n * PLANE_N + cb * 32;
        const __nv_bfloat16* hl = g_hl + (size_t)n * PLANE_N + cb * 32;
        for (int i = tid; i < 6528; i += 256) {
            int c = i & 31;
            int j = i >> 5;               // 0..203
            int rr = j / 34;
            int col = j - rr * 34;
            size_t off = (size_t)((4 * ty + rr) * 34 + col) * CHN + c;
            float v = __bfloat162float(hh[off]) + __bfloat162float(hl[off]);
            s_in[c * 204 + rr * 34 + col] = v;
        }
    }
    __syncthreads();

    // 256 items: c = tid&31, tx = tid>>5 (8 tiles)
    const int c = tid & 31, tx = tid >> 5;
    const float* dd = &s_in[c * 204];
    float d[6][6];
#pragma unroll
    for (int r = 0; r < 6; r++)
#pragma unroll
        for (int cc = 0; cc < 6; cc++)
            d[r][cc] = dd[r * 34 + 4 * tx + cc];
    // rows: w = BT d
    float w[6][6];
#pragma unroll
    for (int cc = 0; cc < 6; cc++) {
        float d0 = d[0][cc], d1 = d[1][cc], d2 = d[2][cc];
        float d3 = d[3][cc], d4 = d[4][cc], d5 = d[5][cc];
        w[0][cc] = 4.f * d0 - 5.f * d2 + d4;
        w[1][cc] = -4.f * d1 - 4.f * d2 + d3 + d4;
        w[2][cc] = 4.f * d1 - 4.f * d2 - d3 + d4;
        w[3][cc] = -2.f * d1 - d2 + 2.f * d3 + d4;
        w[4][cc] = 2.f * d1 - d2 - 2.f * d3 + d4;
        w[5][cc] = 4.f * d1 - 5.f * d3 + d5;
    }
    int gtile = n * 64 + ty * 8 + tx;
    int ch = cb * 32 + c;
#pragma unroll
    for (int r = 0; r < 6; r++) {
        float d0 = w[r][0], d1 = w[r][1], d2 = w[r][2];
        float d3 = w[r][3], d4 = w[r][4], d5 = w[r][5];
        float v[6];
        v[0] = 4.f * d0 - 5.f * d2 + d4;
        v[1] = -4.f * d1 - 4.f * d2 + d3 + d4;
        v[2] = 4.f * d1 - 4.f * d2 - d3 + d4;
        v[3] = -2.f * d1 - d2 + 2.f * d3 + d4;
        v[4] = 2.f * d1 - d2 - 2.f * d3 + d4;
        v[5] = 4.f * d1 - 5.f * d3 + d5;
#pragma unroll
        for (int j = 0; j < 6; j++) {
            int t = r * 6 + j;
            size_t off = ((size_t)t * NTILE + gtile) * CHN + ch;
            split_store(g_Vh, g_Vl, off, v[j]);
        }
    }
}

// ======================= Winograd GEMM (bf16x3 mma.sync) ===================
// C[oc 128][tile 128] = U_t[128,512] * V_t[128,512]^T. grid (8, 4, 36).
__global__ void __launch_bounds__(256, 2)
gemm_wino_kernel(int which) {
    extern __shared__ __align__(16) char dynsm[];
    const uint32_t smbase = smem_u32(dynsm);

    const int tid = threadIdx.x;
    const int lane = tid & 31, warp = tid >> 5;
    const int wm = warp >> 2, wn = warp & 3;
    const int nt0 = blockIdx.x * 128;
    const int oc0 = blockIdx.y * 128;
    const int t = blockIdx.z;

    const __nv_bfloat16* Uh = (which == 1) ? g_U1h : g_U2h;
    const __nv_bfloat16* Ul = (which == 1) ? g_U1l : g_U2l;

    const int frow = tid >> 1, fhalf = tid & 1;

    const int lt = lane >> 3, lr = lane & 7;
    const int a_row_off = (lt & 1) * 8 + lr;
    const int a_col_off = (lt >> 1) * 8;
    const int b_row_off = (lt >> 1) * 8 + lr;
    const int b_col_off = (lt & 1) * 8;

    float C[4][4][4];
#pragma unroll
    for (int mi = 0; mi < 4; mi++)
#pragma unroll
        for (int ni = 0; ni < 4; ni++)
#pragma unroll
            for (int q = 0; q < 4; q++) C[mi][ni][q] = 0.f;

    auto fill = [&](int chunk, int stage) {
        const int k0 = chunk << 5;
        const uint32_t sb = smbase + stage * STAGE_BYTES;
        {
            size_t o = ((size_t)t * CHN + oc0 + frow) * CHN + k0 + fhalf * 16;
            uint32_t d = sb + frow * 80 + fhalf * 32;
            cp_async16(d, Uh + o);
            cp_async16(d + 16, Uh + o + 8);
            cp_async16(d + OFF_AL, Ul + o);
            cp_async16(d + OFF_AL + 16, Ul + o + 8);
        }
        {
            size_t o = ((size_t)t * NTILE + nt0 + frow) * CHN + k0 + fhalf * 16;
            uint32_t d = sb + frow * 80 + fhalf * 32;
            cp_async16(d + OFF_BH, g_Vh + o);
            cp_async16(d + OFF_BH + 16, g_Vh + o + 8);
            cp_async16(d + OFF_BL, g_Vl + o);
            cp_async16(d + OFF_BL + 16, g_Vl + o + 8);
        }
    };

    fill(0, 0); CP_COMMIT();
    fill(1, 1); CP_COMMIT();

    for (int chunk = 0; chunk < NCHUNK; ++chunk) {
        const int stage = chunk & 1;
        if (chunk == NCHUNK - 1) { CP_WAIT(0); } else { CP_WAIT(1); }
        __syncthreads();

        const uint32_t sb = smbase + stage * STAGE_BYTES;
#pragma unroll
        for (int s = 0; s < 2; ++s) {
            const int kk0 = s * 16;
            uint32_t Af[4][4], Bhf[2][4], Blf[2][4];
#pragma unroll
            for (int mi = 0; mi < 4; mi++) {
                int row = wm * 64 + mi * 16 + a_row_off;
                ldm_x4(Af[mi], sb + (uint32_t)(row * AP + kk0 + a_col_off) * 2);
            }
#pragma unroll
            for (int g = 0; g < 2; g++) {
                int row = wn * 32 + g * 16 + b_row_off;
                uint32_t off = (uint32_t)(row * AP + kk0 + b_col_off) * 2;
                ldm_x4(Bhf[g], sb + OFF_BH + off);
                ldm_x4(Blf[g], sb + OFF_BL + off);
            }
#pragma unroll
            for (int mi = 0; mi < 4; mi++)
#pragma unroll
                for (int ni = 0; ni < 4; ni++)
                    mma_bf16(C[mi][ni], Af[mi],
                             Bhf[ni >> 1][(ni & 1) * 2],
                             Bhf[ni >> 1][(ni & 1) * 2 + 1]);
#pragma unroll
            for (int mi = 0; mi < 4; mi++)
#pragma unroll
                for (int ni = 0; ni < 4; ni++)
                    mma_bf16(C[mi][ni], Af[mi],
                             Blf[ni >> 1][(ni & 1) * 2],
                             Blf[ni >> 1][(ni & 1) * 2 + 1]);
#pragma unroll
            for (int mi = 0; mi < 4; mi++) {
                int row = wm * 64 + mi * 16 + a_row_off;
                ldm_x4(Af[mi],
                       sb + OFF_AL + (uint32_t)(row * AP + kk0 + a_col_off) * 2);
            }
#pragma unroll
            for (int mi = 0; mi < 4; mi++)
#pragma unroll
                for (int ni = 0; ni < 4; ni++)
                    mma_bf16(C[mi][ni], Af[mi],
                             Bhf[ni >> 1][(ni & 1) * 2],
                             Bhf[ni >> 1][(ni & 1) * 2 + 1]);
        }

        if (chunk + 2 < NCHUNK) {
            __syncthreads();
            fill(chunk + 2, stage);
            CP_COMMIT();
        }
    }

    // epilogue: transpose through smem -> g_M[t][tile][oc]
    __syncthreads();
    float* sC = reinterpret_cast<float*>(dynsm);       // pitch 132
    const int g = lane >> 2, t4 = lane & 3;
#pragma unroll
    for (int mi = 0; mi < 4; mi++) {
        int ocA = wm * 64 + mi * 16 + g;
        int ocB = ocA + 8;
#pragma unroll
        for (int ni = 0; ni < 4; ni++) {
            int nn = wn * 32 + ni * 8 + t4 * 2;
            sC[nn * 132 + ocA] = C[mi][ni][0];
            sC[(nn + 1) * 132 + ocA] = C[mi][ni][1];
            sC[nn * 132 + ocB] = C[mi][ni][2];
            sC[(nn + 1) * 132 + ocB] = C[mi][ni][3];
        }
    }
    __syncthreads();
    float* Mo = g_M + ((size_t)t * NTILE + nt0) * CHN + oc0;
    for (int e = tid; e < 16384; e += 256) {
        int tl = e >> 7, ocl = e & 127;
        Mo[(size_t)tl * CHN + ocl] = sC[tl * 132 + ocl];
    }
}

// ======================= output transform helpers ==========================
__device__ __forceinline__ void at_rows(const float m[6], float o[4]) {
    o[0] = m[0] + m[1] + m[2] + m[3] + m[4];
    o[1] = m[1] - m[2] + 2.f * m[3] - 2.f * m[4];
    o[2] = m[1] + m[2] + 4.f * m[3] + 4.f * m[4];
    o[3] = m[1] - m[2] + 8.f * m[3] - 8.f * m[4] + m[5];
}

// ======================= output transform, conv1 ===========================
// grid (4 ocq, 8 ty, 16 n), block 256, 4 iters (128 oc x 8 tx).
__global__ void __launch_bounds__(256)
outx1_kernel() {
    const int ocq = blockIdx.x, ty = blockIdx.y, n = blockIdx.z;
    const int tid = threadIdx.x;
    __nv_bfloat16* hh = g_hh + (size_t)n * PLANE_N;
    __nv_bfloat16* hl = g_hl + (size_t)n * PLANE_N;
#pragma unroll
    for (int it = 0; it < 4; it++) {
        int item = tid + it * 256;        // 1024 = 8 tx * 128 oc
        int oc = ocq * 128 + (item & 127);
        int tx = item >> 7;
        int gtile = n * 64 + ty * 8 + tx;
        float m[36];
#pragma unroll
        for (int t = 0; t < 36; t++)
            m[t] = g_M[((size_t)t * NTILE + gtile) * CHN + oc];
        // rows: tmp = AT (6x6 m) -> 4x6
        float tmp[4][6];
#pragma unroll
        for (int j = 0; j < 6; j++) {
            float col[6];
#pragma unroll
            for (int i = 0; i < 6; i++) col[i] = m[i * 6 + j];
            float o[4];
            at_rows(col, o);
#pragma unroll
            for (int i = 0; i < 4; i++) tmp[i][j] = o[i];
        }
        float s = g_bns[oc], b = g_bnb[oc];
#pragma unroll
        for (int i = 0; i < 4; i++) {
            float o[4];
            at_rows(tmp[i], o);
#pragma unroll
            for (int j = 0; j < 4; j++) {
                float v = fmaxf(fmaf(o[j], s, b), 0.f);
                int pos = (4 * ty + i + 1) * 34 + (4 * tx + j + 1);
                split_store(hh, hl, (size_t)pos * CHN + oc, v);
            }
        }
    }
}

// ======================= output transform, conv2 -> x_enc fp32 =============
// grid (8 ocq, 8 ty, 16 n), block 256; 64 oc x 8 tx; smem transpose.
__global__ void __launch_bounds__(256)
outx2_kernel(float* __restrict__ out) {
    __shared__ float sO[64][132];         // [oc_l][yy*33 + col]
    const int ocq = blockIdx.x, ty = blockIdx.y, n = blockIdx.z;
    const int tid = threadIdx.x;
#pragma unroll
    for (int it = 0; it < 2; it++) {
        int item = tid + it * 256;        // 512 = 8 tx * 64 oc
        int ocl = item & 63;
        int tx = item >> 6;
        int oc = ocq * 64 + ocl;
        int gtile = n * 64 + ty * 8 + tx;
        float m[36];
#pragma unroll
        for (int t = 0; t < 36; t++)
            m[t] = g_M[((size_t)t * NTILE + gtile) * CHN + oc];
        float tmp[4][6];
#pragma unroll
        for (int j = 0; j < 6; j++) {
            float col[6];
#pragma unroll
            for (int i = 0; i < 6; i++) col[i] = m[i * 6 + j];
            float o[4];
            at_rows(col, o);
#pragma unroll
            for (int i = 0; i < 4; i++) tmp[i][j] = o[i];
        }
#pragma unroll
        for (int i = 0; i < 4; i++) {
            float o[4];
            at_rows(tmp[i], o);
#pragma unroll
            for (int j = 0; j < 4; j++)
                sO[ocl][i * 33 + 4 * tx + j] = o[j];
        }
    }
    __syncthreads();
    float* oN = out + ((size_t)n * CHN + ocq * 64) * HWP;
    for (int e = tid; e < 8192; e += 256) {
        int ocl = e >> 7;
        int r2 = e & 127;
        int yy = r2 >> 5, col = r2 & 31;
        oN[(size_t)ocl * HWP + (4 * ty + yy) * 32 + col] = sO[ocl][yy * 33 + col];
    }
}

// ======================= assign + softmax (split-K x2) =====================
__global__ void __launch_bounds__(256)
assign_softmax_kernel(const float* __restrict__ xenc, const float* __restrict__ wa) {
    __shared__ float s_w[2][8][64];
    __shared__ float s_part[128][65];
    const int n = blockIdx.x >> 3;
    const int l0 = (blockIdx.x & 7) * 128;
    const int tid = threadIdx.x;
    const int grp = tid >> 7;
    const int lt = tid & 127;
    const int l = l0 + lt;
    const int cbase = grp * 256;
    const float* xN = xenc + (size_t)n * CHN * HWP;

    float s[64];
#pragma unroll
    for (int k = 0; k < 64; k++) s[k] = 0.f;
    float ss = 0.f;

    for (int c0 = 0; c0 < 256; c0 += 8) {
#pragma unroll
        for (int r = 0; r < 4; r++) {
            int idx = lt + r * 128;
            int cc = idx >> 6, k = idx & 63;
            s_w[grp][cc][k] = wa[k * 512 + cbase + c0 + cc];
        }
        __syncthreads();
#pragma unroll
        for (int cc = 0; cc < 8; cc++) {
            float xv = xN[(cbase + c0 + cc) * HWP + l];
            ss = fmaf(xv, xv, ss);
#pragma unroll
            for (int k = 0; k < 64; k++) s[k] = fmaf(xv, s_w[grp][cc][k], s[k]);
        }
        __syncthreads();
    }

    if (grp == 1) {
#pragma unroll
        for (int k = 0; k < 64; k++) s_part[lt][k] = s[k];
        s_part[lt][64] = ss;
    }
    __syncthreads();
    if (grp == 0) {
#pragma unroll
        for (int k = 0; k < 64; k++) s[k] += s_part[lt][k];
        ss += s_part[lt][64];

        float invn = 1.f / fmaxf(sqrtf(ss), 1e-12f);
        g_invn[n * HWP + l] = invn;

        float mx = -1e30f;
#pragma unroll
        for (int k = 0; k < 64; k++) { s[k] *= invn; mx = fmaxf(mx, s[k]); }
        float sum = 0.f;
#pragma unroll
        for (int k = 0; k < 64; k++) { s[k] = expf(s[k] - mx); sum += s[k]; }
        float rs = 1.f / sum;
#pragma unroll
        for (int k = 0; k < 64; k++)
            g_sa[((size_t)n * 64 + k) * HWP + l] = s[k] * rs;
    }
}

// ======================= ssum =======================
__global__ void ssum_kernel() {
    int row = blockIdx.x;
    int tid = threadIdx.x;
    const float4* p = reinterpret_cast<const float4*>(g_sa + (size_t)row * HWP);
    float4 v = p[tid];
    float t = v.x + v.y + v.z + v.w;
    __shared__ float red[256];
    red[tid] = t;
    __syncthreads();
    for (int s = 128; s > 0; s >>= 1) {
        if (tid < s) red[tid] += red[tid + s];
        __syncthreads();
    }
    if (tid == 0) g_ssum[row] = red[0];
}

// ======================= VLAD =======================
__global__ void __launch_bounds__(256)
vlad_kernel(const float* __restrict__ xenc, const float* __restrict__ cent) {
    __shared__ float s_sa[8][1024];
    __shared__ float s_in[1024];
    const int n = blockIdx.x >> 3;
    const int k0 = (blockIdx.x & 7) * 8;
    const int tid = threadIdx.x;

    for (int i = tid; i < 1024; i += 256) s_in[i] = g_invn[n * HWP + i];
    for (int i = tid; i < 8192; i += 256) {
        int kk = i >> 10, l = i & 1023;
        s_sa[kk][l] = g_sa[((size_t)n * 64 + k0 + kk) * HWP + l];
    }
    __syncthreads();

    const int warp = tid >> 5, lane = tid & 31;
    const float* xN = xenc + (size_t)n * CHN * HWP;

    for (int c = warp; c < 512; c += 8) {
        float acc[8];
#pragma unroll
        for (int kk = 0; kk < 8; kk++) acc[kk] = 0.f;
        for (int l = lane; l < 1024; l += 32) {
            float xv = xN[c * HWP + l] * s_in[l];
#pragma unroll
            for (int kk = 0; kk < 8; kk++) acc[kk] = fmaf(xv, s_sa[kk][l], acc[kk]);
        }
#pragma unroll
        for (int kk = 0; kk < 8; kk++) {
            float v = acc[kk];
#pragma unroll
            for (int o = 16; o > 0; o >>= 1) v += __shfl_down_sync(0xffffffffu, v, o);
            if (lane == 0) {
                int k = k0 + kk;
                g_vlad[((size_t)n * 64 + k) * 512 + c] =
                    v - g_ssum[n * 64 + k] * cent[k * 512 + c];
            }
        }
    }
}

// ======================= intra norm =======================
__global__ void intra_kernel(float* __restrict__ out_vlad) {
    int row = blockIdx.x;
    int tid = threadIdx.x;
    const float2* p = reinterpret_cast<const float2*>(g_vlad + (size_t)row * 512);
    float2 v = p[tid];
    float ssq = v.x * v.x + v.y * v.y;
    __shared__ float red[256];
    red[tid] = ssq;
    __syncthreads();
    for (int s = 128; s > 0; s >>= 1) {
        if (tid < s) red[tid] += red[tid + s];
        __syncthreads();
    }
    float ss = red[0];
    float inv = 1.f / fmaxf(sqrtf(ss), 1e-12f);
    float2* o = reinterpret_cast<float2*>(out_vlad + (size_t)row * 512);
    float2 w;
    w.x = v.x * inv;
    w.y = v.y * inv;
    o[tid] = w;
    if (tid == 0) g_rowss[row] = ss * inv * inv;
}

// ======================= global scale =======================
__global__ void gscale_kernel(float* __restrict__ out_vlad) {
    int n = blockIdx.x;
    int tid = threadIdx.x;
    __shared__ float red[64];
    __shared__ float gsc;
    if (tid < 64) red[tid] = g_rowss[n * 64 + tid];
    __syncthreads();
    if (tid == 0) {
        float t = 0.f;
        for (int i = 0; i < 64; i++) t += red[i];
        gsc = 1.f / fmaxf(sqrtf(t), 1e-12f);
    }
    __syncthreads();
    float g = gsc;
    float* o = out_vlad + (size_t)n * (KCL * CHN);
    for (int i = tid; i < KCL * CHN; i += 256) o[i] *= g;
}

// ======================= launcher =======================
extern "C" void kernel_launch(void* const* d_in, const int* in_sizes, int n_in,
                              void* d_out, int out_size) {
    const float* x     = (const float*)d_in[0];
    const float* w1    = (const float*)d_in[1];
    const float* gamma = (const float*)d_in[2];
    const float* beta  = (const float*)d_in[3];
    const float* mean  = (const float*)d_in[4];
    const float* var   = (const float*)d_in[5];
    const float* w2    = (const float*)d_in[6];
    const float* wa    = (const float*)d_in[7];
    const float* cent  = (const float*)d_in[8];

    float* out = (float*)d_out;
    float* out_vlad = out;
    float* out_xenc = out + (size_t)N_IMG * KCL * CHN;

    static int smem_set = 0;
    if (!smem_set) {
        cudaFuncSetAttribute(gemm_wino_kernel,
                             cudaFuncAttributeMaxDynamicSharedMemorySize,
                             GEMM_DSMEM);
        smem_set = 1;
    }

    prep_wino_kernel<<<2048, 256>>>(w1, w2, gamma, beta, mean, var);

    dim3 tgrid(16, 8, N_IMG);
    dim3 ggrid(8, 4, NT);
    dim3 o1grid(4, 8, N_IMG);
    dim3 o2grid(8, 8, N_IMG);

    inx_kernel<<<tgrid, 256>>>(x, 1);
    gemm_wino_kernel<<<ggrid, 256, GEMM_DSMEM>>>(1);
    outx1_kernel<<<o1grid, 256>>>();

    inx_kernel<<<tgrid, 256>>>(nullptr, 2);
    gemm_wino_kernel<<<ggrid, 256, GEMM_DSMEM>>>(2);
    outx2_kernel<<<o2grid, 256>>>(out_xenc);

    assign_softmax_kernel<<<N_IMG * 8, 256>>>(out_xenc, wa);
    ssum_kernel<<<N_IMG * KCL, 256>>>();
    vlad_kernel<<<N_IMG * 8, 256>>>(out_xenc, cent);
    intra_kernel<<<N_IMG * KCL, 256>>>(out_vlad);
    gscale_kernel<<<N_IMG, 256>>>(out_vlad);
}